// round 4
// baseline (speedup 1.0000x reference)
#include <cuda_runtime.h>

// Problem constants: N = 524288 rows, NCH = 30 channels, 8 gases.
// out[n, c, k] = cons[n,k] * exp(w_gas[k,c]) * (k<2 ? 1 : FILTERS[k-2,c] * s[k-2,n])
// s[g,n] = sigmoid(MLP_g(tpl[n,0:2]))  -- per-group 2->6->4->4->1 MLP.

#define RPB 256  // rows per block == threads per block

__device__ __constant__ float FILT[6][30] = {
 {1,1,1,1,1,1,1,1,1,1,1,1,1,1,1,1,1,1,1,1,1,1,0,0,0,0,0,0,1,1},
 {1,1,0,0,0,0,0,0,0,0,0,0,0,0,0,0,1,1,1,1,1,1,0,0,1,1,1,1,1,1},
 {1,1,0,0,1,1,0,0,1,1,0,0,1,1,0,0,0,0,0,0,0,0,0,0,0,0,0,0,1,1},
 {1,1,0,0,0,0,0,0,0,0,0,0,0,0,1,1,1,1,1,1,1,1,0,0,0,0,1,1,1,1},
 {1,1,0,0,1,0,0,0,0,0,0,0,0,0,0,0,0,0,0,0,0,0,0,0,0,0,0,0,1,1},
 {1,1,1,1,0,0,1,1,0,0,1,1,0,0,0,0,0,0,0,0,0,0,0,0,0,0,0,0,1,1}};

__global__ void __launch_bounds__(RPB)
extinction_kernel(
    const float* __restrict__ tpl,   // (N,3)
    const float* __restrict__ cons,  // (N,8)
    const float* __restrict__ wgas,  // (8,30)
    const float* __restrict__ W1,    // (6,6,2)
    const float* __restrict__ B1,    // (6,6)
    const float* __restrict__ W2,    // (6,4,6)
    const float* __restrict__ B2,    // (6,4)
    const float* __restrict__ W3,    // (6,4,4)
    const float* __restrict__ B3,    // (6,4)
    const float* __restrict__ Wo,    // (6,4)
    const float* __restrict__ Bo,    // (6,)
    float* __restrict__ out,         // (N,30,8)
    int nrows)
{
    // EF table laid out [c][k] so a lane's float4 is sEF4[c*2 + k0/4].
    __shared__ float4 sEF4[60];                 // 240 floats = exp(w_gas).T with filters folded in
    __shared__ float  sW1[72], sB1[36], sW2[144], sB2[24],
                      sW3[96], sB3[24], sWo[24], sBo[8];
    __shared__ float  sS[RPB][6];               // sigmoid outputs per row
    __shared__ float4 sC[RPB][2];               // cons per row (8 floats)

    const int tid = threadIdx.x;
    float* sEF = (float*)sEF4;

    // ---- Prologue: weights + fused exp/filter table into SMEM ----
    if (tid < 240) {
        int c = tid >> 3, k = tid & 7;
        float e = __expf(wgas[k * 30 + c]);
        if (k >= 2) e *= FILT[k - 2][c];
        sEF[tid] = e;
    }
    if (tid < 72)  sW1[tid] = W1[tid];
    if (tid < 36)  sB1[tid] = B1[tid];
    if (tid < 144) sW2[tid] = W2[tid];
    if (tid < 96)  sW3[tid] = W3[tid];          // fix for R1's rel_err 3.3e-2
    if (tid < 24) { sB2[tid] = B2[tid]; sB3[tid] = B3[tid]; sWo[tid] = Wo[tid]; }
    if (tid < 6)   sBo[tid] = Bo[tid];

    const int base = blockIdx.x * RPB;
    const int n = base + tid;
    float x0 = 0.f, x1 = 0.f;
    if (n < nrows) {
        const float4* cp = (const float4*)cons + n * 2;
        sC[tid][0] = cp[0];
        sC[tid][1] = cp[1];
        x0 = tpl[n * 3 + 0];
        x1 = tpl[n * 3 + 1];
    }
    __syncthreads();

    // ---- Phase 1: per-row MLP (one thread = one row), fully unrolled ----
    if (n < nrows) {
        #pragma unroll
        for (int g = 0; g < 6; g++) {
            float h1[6];
            #pragma unroll
            for (int j = 0; j < 6; j++) {
                float a = fmaf(sW1[g*12 + j*2 + 0], x0,
                          fmaf(sW1[g*12 + j*2 + 1], x1, sB1[g*6 + j]));
                h1[j] = fmaxf(a, 0.f);
            }
            float h2[4];
            #pragma unroll
            for (int o = 0; o < 4; o++) {
                float a = sB2[g*4 + o];
                #pragma unroll
                for (int j = 0; j < 6; j++) a = fmaf(sW2[g*24 + o*6 + j], h1[j], a);
                h2[o] = fmaxf(a, 0.f);
            }
            float h3[4];
            #pragma unroll
            for (int p = 0; p < 4; p++) {
                float a = sB3[g*4 + p];
                #pragma unroll
                for (int o = 0; o < 4; o++) a = fmaf(sW3[g*16 + p*4 + o], h2[o], a);
                h3[p] = fmaxf(a, 0.f);
            }
            float z = sBo[g];
            #pragma unroll
            for (int p = 0; p < 4; p++) z = fmaf(sWo[g*4 + p], h3[p], z);
            sS[tid][g] = 1.0f / (1.0f + __expf(-z));
        }
    }
    __syncthreads();

    // ---- Phase 2: warp-cooperative coalesced stores ----
    // Row = 240 floats = 60 float4. Lane l writes float4 j4 = l and j4 = 32+l (l<28).
    // For j4: c = j4>>1, k0 = (j4&1)*4. Both EF vectors and the parity select are
    // lane-invariant across rows -> hoisted out of the row loop.
    const int warp = tid >> 5;
    const int lane = tid & 31;
    const bool odd = (lane & 1);
    const float4 efA = sEF4[lane];
    float4 efB = make_float4(0.f, 0.f, 0.f, 0.f);
    const bool hasB = (lane < 28);
    if (hasB) efB = sEF4[32 + lane];

    float4* __restrict__ ob = (float4*)out;

    #pragma unroll 4
    for (int rr = 0; rr < 32; rr++) {
        const int row = warp * 32 + rr;
        const int nr = base + row;
        if (nr < nrows) {
            const float4 c0 = sC[row][0];
            const float4 c1 = sC[row][1];
            const float s0 = sS[row][0], s1 = sS[row][1], s2 = sS[row][2];
            const float s3 = sS[row][3], s4 = sS[row][4], s5 = sS[row][5];
            // k0==0 lanes: factors (1,1,s0,s1); k0==4 lanes: (s2,s3,s4,s5)
            const float f0 = odd ? s2 : 1.f;
            const float f1 = odd ? s3 : 1.f;
            const float f2 = odd ? s4 : s0;
            const float f3 = odd ? s5 : s1;
            const float4 cv = odd ? c1 : c0;
            const long ofs = (long)nr * 60;

            float4 v;
            v.x = cv.x * efA.x * f0;
            v.y = cv.y * efA.y * f1;
            v.z = cv.z * efA.z * f2;
            v.w = cv.w * efA.w * f3;
            __stcs(&ob[ofs + lane], v);

            if (hasB) {
                float4 w;
                w.x = cv.x * efB.x * f0;
                w.y = cv.y * efB.y * f1;
                w.z = cv.z * efB.z * f2;
                w.w = cv.w * efB.w * f3;
                __stcs(&ob[ofs + 32 + lane], w);
            }
        }
    }
}

extern "C" void kernel_launch(void* const* d_in, const int* in_sizes, int n_in,
                              void* d_out, int out_size) {
    const float* tpl  = (const float*)d_in[0];
    const float* cons = (const float*)d_in[1];
    const float* wgas = (const float*)d_in[2];
    const float* W1   = (const float*)d_in[3];
    const float* B1   = (const float*)d_in[4];
    const float* W2   = (const float*)d_in[5];
    const float* B2   = (const float*)d_in[6];
    const float* W3   = (const float*)d_in[7];
    const float* B3   = (const float*)d_in[8];
    const float* Wo   = (const float*)d_in[9];
    const float* Bo   = (const float*)d_in[10];

    const int nrows = in_sizes[0] / 3;        // tpl is (N,3)
    const int blocks = (nrows + RPB - 1) / RPB;

    extinction_kernel<<<blocks, RPB>>>(
        tpl, cons, wgas, W1, B1, W2, B2, W3, B3, Wo, Bo,
        (float*)d_out, nrows);
}

// round 6
// speedup vs baseline: 1.0037x; 1.0037x over previous
#include <cuda_runtime.h>

// Problem constants: N = 524288 rows, NCH = 30 channels, 8 gases.
// out[n, c, k] = cons[n,k] * exp(w_gas[k,c]) * (k<2 ? 1 : FILTERS[k-2,c] * s[k-2,n])
// s[g,n] = sigmoid(MLP_g(tpl[n,0:2]))  -- per-group 2->6->4->4->1 MLP.
//
// Factorization: out[n, c, k] = EF[c][k] * CF[n][k]
//   EF[c][k] = exp(w_gas[k,c]) * (k<2 ? 1 : FILTERS[k-2][c])   (240 floats, per-launch)
//   CF[n][k] = cons[n,k] * (k<2 ? 1 : s[k-2,n])                 (8 floats per row)

#define RPB 256  // rows per block == threads per block

__device__ __constant__ float FILT[6][30] = {
 {1,1,1,1,1,1,1,1,1,1,1,1,1,1,1,1,1,1,1,1,1,1,0,0,0,0,0,0,1,1},
 {1,1,0,0,0,0,0,0,0,0,0,0,0,0,0,0,1,1,1,1,1,1,0,0,1,1,1,1,1,1},
 {1,1,0,0,1,1,0,0,1,1,0,0,1,1,0,0,0,0,0,0,0,0,0,0,0,0,0,0,1,1},
 {1,1,0,0,0,0,0,0,0,0,0,0,0,0,1,1,1,1,1,1,1,1,0,0,0,0,1,1,1,1},
 {1,1,0,0,1,0,0,0,0,0,0,0,0,0,0,0,0,0,0,0,0,0,0,0,0,0,0,0,1,1},
 {1,1,1,1,0,0,1,1,0,0,1,1,0,0,0,0,0,0,0,0,0,0,0,0,0,0,0,0,1,1}};

__global__ void __launch_bounds__(RPB)
extinction_kernel(
    const float* __restrict__ tpl,   // (N,3)
    const float* __restrict__ cons,  // (N,8)
    const float* __restrict__ wgas,  // (8,30)
    const float* __restrict__ W1,    // (6,6,2)
    const float* __restrict__ B1,    // (6,6)
    const float* __restrict__ W2,    // (6,4,6)
    const float* __restrict__ B2,    // (6,4)
    const float* __restrict__ W3,    // (6,4,4)
    const float* __restrict__ B3,    // (6,4)
    const float* __restrict__ Wo,    // (6,4)
    const float* __restrict__ Bo,    // (6,)
    float* __restrict__ out,         // (N,30,8)
    int nrows)
{
    // EF table laid out [c][k]: element float4 j covers channel j>>1, gases (j&1)*4..+3.
    __shared__ float4 sEF4[60];                  // exp(w_gas).T with filters folded in
    __shared__ float  sW1[72], sB1[36], sW2[144], sB2[24],
                      sW3[96], sB3[24], sWo[24], sBo[8];
    __shared__ float4 sCF[RPB][2];               // per-row cons * sigmoid factors

    const int tid = threadIdx.x;
    float* sEF = (float*)sEF4;

    // ---- Prologue: weights + fused exp/filter table into SMEM ----
    if (tid < 240) {
        int c = tid >> 3, k = tid & 7;
        float e = __expf(wgas[k * 30 + c]);
        if (k >= 2) e *= FILT[k - 2][c];
        sEF[tid] = e;
    }
    if (tid < 72)  sW1[tid] = W1[tid];
    if (tid < 36)  sB1[tid] = B1[tid];
    if (tid < 144) sW2[tid] = W2[tid];
    if (tid < 96)  sW3[tid] = W3[tid];
    if (tid < 24) { sB2[tid] = B2[tid]; sB3[tid] = B3[tid]; sWo[tid] = Wo[tid]; }
    if (tid < 6)   sBo[tid] = Bo[tid];

    const int base = blockIdx.x * RPB;
    const int n = base + tid;
    float x0 = 0.f, x1 = 0.f;
    float4 c0 = make_float4(0.f,0.f,0.f,0.f), c1 = c0;
    if (n < nrows) {
        const float4* cp = (const float4*)cons + n * 2;
        c0 = cp[0];
        c1 = cp[1];
        x0 = tpl[n * 3 + 0];
        x1 = tpl[n * 3 + 1];
    }
    __syncthreads();

    // ---- Phase 1: per-row MLP (one thread = one row), fully unrolled.
    //      Folds cons * sigmoid factors into sCF[row]. ----
    if (n < nrows) {
        float s[6];
        #pragma unroll
        for (int g = 0; g < 6; g++) {
            float h1[6];
            #pragma unroll
            for (int j = 0; j < 6; j++) {
                float a = fmaf(sW1[g*12 + j*2 + 0], x0,
                          fmaf(sW1[g*12 + j*2 + 1], x1, sB1[g*6 + j]));
                h1[j] = fmaxf(a, 0.f);
            }
            float h2[4];
            #pragma unroll
            for (int o = 0; o < 4; o++) {
                float a = sB2[g*4 + o];
                #pragma unroll
                for (int j = 0; j < 6; j++) a = fmaf(sW2[g*24 + o*6 + j], h1[j], a);
                h2[o] = fmaxf(a, 0.f);
            }
            float h3[4];
            #pragma unroll
            for (int p = 0; p < 4; p++) {
                float a = sB3[g*4 + p];
                #pragma unroll
                for (int o = 0; o < 4; o++) a = fmaf(sW3[g*16 + p*4 + o], h2[o], a);
                h3[p] = fmaxf(a, 0.f);
            }
            float z = sBo[g];
            #pragma unroll
            for (int p = 0; p < 4; p++) z = fmaf(sWo[g*4 + p], h3[p], z);
            s[g] = 1.0f / (1.0f + __expf(-z));
        }
        float4 cf0, cf1;
        cf0.x = c0.x;          // k=0: factor 1
        cf0.y = c0.y;          // k=1: factor 1
        cf0.z = c0.z * s[0];   // k=2
        cf0.w = c0.w * s[1];   // k=3
        cf1.x = c1.x * s[2];   // k=4
        cf1.y = c1.y * s[3];   // k=5
        cf1.z = c1.z * s[4];   // k=6
        cf1.w = c1.w * s[5];   // k=7
        sCF[tid][0] = cf0;
        sCF[tid][1] = cf1;
    }
    __syncthreads();

    // ---- Phase 2: chunk-contiguous coalesced stores ----
    // Block output span = 256 rows * 60 float4 = 15360 float4 (245760 B, 128B-aligned).
    // Warp w owns the contiguous sub-span [w*1920, (w+1)*1920) = exactly 32 rows.
    // Iteration i, lane l emits flat float4 index p = i*32 + l of the warp chunk:
    //   row_local = warp*32 + p/60, r4 = p%60  (tracked incrementally).
    // Every warp-wide STG.128 is a full 512B-aligned span: 4 complete lines, no idle lanes.
    const int warp = tid >> 5;
    const int lane = tid & 31;

    int r4  = lane;          // p % 60 (p = lane at i=0, lane < 60)
    int row = warp * 32;     // local row = warp*32 + p/60
    int gi  = base * 60 + warp * 1920 + lane;   // global float4 index
    const int limit4 = nrows * 60;
    float4* __restrict__ op = (float4*)out + gi;

    #pragma unroll 15
    for (int i = 0; i < 60; i++) {
        const float4 ef = sEF4[r4];
        const float4 cf = sCF[row][r4 & 1];
        float4 v;
        v.x = ef.x * cf.x;
        v.y = ef.y * cf.y;
        v.z = ef.z * cf.z;
        v.w = ef.w * cf.w;
        if (gi < limit4) __stcs(op, v);
        op += 32;
        gi += 32;
        r4 += 32;
        if (r4 >= 60) { r4 -= 60; row++; }
    }
}

extern "C" void kernel_launch(void* const* d_in, const int* in_sizes, int n_in,
                              void* d_out, int out_size) {
    const float* tpl  = (const float*)d_in[0];
    const float* cons = (const float*)d_in[1];
    const float* wgas = (const float*)d_in[2];
    const float* W1   = (const float*)d_in[3];
    const float* B1   = (const float*)d_in[4];
    const float* W2   = (const float*)d_in[5];
    const float* B2   = (const float*)d_in[6];
    const float* W3   = (const float*)d_in[7];
    const float* B3   = (const float*)d_in[8];
    const float* Wo   = (const float*)d_in[9];
    const float* Bo   = (const float*)d_in[10];

    const int nrows = in_sizes[0] / 3;        // tpl is (N,3)
    const int blocks = (nrows + RPB - 1) / RPB;

    extinction_kernel<<<blocks, RPB>>>(
        tpl, cons, wgas, W1, B1, W2, B2, W3, B3, Wo, Bo,
        (float*)d_out, nrows);
}